// round 1
// baseline (speedup 1.0000x reference)
#include <cuda_runtime.h>
#include <cuda_bf16.h>

// Trilinear scatter-add (Gridding).
// Inputs: d_in[0] = ptcloud float32 [B, N, 3], d_in[1] = scale (int32 scalar).
// Output: d_out = float32 [B, G^3], G = 2*(scale/2).
//
// Strategy:
//   1. cudaMemsetAsync zeroes the output (graph-capturable memset node).
//   2. One thread per point computes the 8 trilinear corner weights and does
//      8 atomicAdd (no return -> REDG, fire-and-forget) into the batch grid.
// All shape parameters (s, G, B, N) are derived on-device from scale/out_size,
// so the host side makes no assumptions about the scalar's value.

__global__ void gridding_scatter_kernel(const float* __restrict__ pts,
                                        const int* __restrict__ scale_p,
                                        float* __restrict__ out,
                                        int npts, int out_size) {
    int i = blockIdx.x * blockDim.x + threadIdx.x;
    if (i >= npts) return;

    // Uniform scalars (same for all threads; cheap, promoted to UR path).
    const int scale = *scale_p;
    const int s = scale >> 1;
    const int G = 2 * s;
    const int G2 = G * G;
    const int G3 = G2 * G;
    const int B = out_size / G3;
    const int N = npts / B;

    const int b = i / N;

    // Load the 3 coords (consecutive floats; warp touches 3 lines per LDG).
    const float fs = (float)s;
    const float x = pts[3 * i + 0];
    const float y = pts[3 * i + 1];
    const float z = pts[3 * i + 2];

    const float px = x * fs;
    const float py = y * fs;
    const float pz = z * fs;

    // Reference drops points whose scaled coords sum to exactly 0.
    const float m = (((px + py) + pz) != 0.0f) ? 1.0f : 0.0f;

    const float lx = floorf(px);
    const float ly = floorf(py);
    const float lz = floorf(pz);
    const float fx = px - lx;
    const float fy = py - ly;
    const float fz = pz - lz;

    const int bx = (int)lx + s;
    const int by = (int)ly + s;
    const int bz = (int)lz + s;

    const float wx0 = (1.0f - fx) * m;
    const float wx1 = fx * m;
    const float wy0 = 1.0f - fy;
    const float wy1 = fy;
    const float wz0 = 1.0f - fz;
    const float wz1 = fz;

    const float w00 = wx0 * wy0;
    const float w01 = wx0 * wy1;
    const float w10 = wx1 * wy0;
    const float w11 = wx1 * wy1;

    // Flat base index of the (bx, by, bz) corner in this batch's grid.
    const int base = b * G3 + (bx * G + by) * G + bz;
    float* o = out + base;

    // z-adjacent pairs are contiguous words (usually same 32B sector).
    atomicAdd(o,              w00 * wz0);
    atomicAdd(o + 1,          w00 * wz1);
    atomicAdd(o + G,          w01 * wz0);
    atomicAdd(o + G + 1,      w01 * wz1);
    atomicAdd(o + G2,         w10 * wz0);
    atomicAdd(o + G2 + 1,     w10 * wz1);
    atomicAdd(o + G2 + G,     w11 * wz0);
    atomicAdd(o + G2 + G + 1, w11 * wz1);
}

extern "C" void kernel_launch(void* const* d_in, const int* in_sizes, int n_in,
                              void* d_out, int out_size) {
    const float* pts = (const float*)d_in[0];
    const int* scale_p = (const int*)d_in[1];
    float* out = (float*)d_out;

    const int npts = in_sizes[0] / 3;  // total points across all batches

    // Zero the output grid (poisoned by the harness).
    cudaMemsetAsync(d_out, 0, (size_t)out_size * sizeof(float), 0);

    const int threads = 256;
    const int blocks = (npts + threads - 1) / threads;
    gridding_scatter_kernel<<<blocks, threads>>>(pts, scale_p, out, npts, out_size);
}

// round 2
// speedup vs baseline: 1.3650x; 1.3650x over previous
#include <cuda_runtime.h>
#include <cuda_bf16.h>

// Trilinear scatter-add (Gridding), L2-resident chunked version.
//
// Key idea: zero the output in batch-aligned chunks (~32MB) with a plain
// store kernel (lines land dirty in L2), then immediately scatter that
// chunk's points while the lines are still L2-resident -> atomicAdds hit L2
// instead of round-tripping to DRAM. The zero of chunk c+1 runs on a second
// stream overlapped with the scatter of chunk c (fork/join via events inside
// graph capture), rate-limited so at most 2 chunks (~64MB) are hot at once.
//
// All shape parameters (s, G, B, N, chunk ranges) are derived on-device from
// the scale scalar and out_size — the host makes no shape assumptions.

__device__ __forceinline__ void get_dims(const int* __restrict__ scale_p,
                                         int out_size, int npts,
                                         int& s, int& G, int& G2, int& G3,
                                         int& B, int& N) {
    const int scale = *scale_p;
    s = scale >> 1;
    G = 2 * s;
    G2 = G * G;
    G3 = G2 * G;
    B = out_size / G3;
    N = npts / B;
}

// Zero batches [c*B/C, (c+1)*B/C) of the output with float4 stores.
__global__ void gridding_zero_chunk(float* __restrict__ out,
                                    const int* __restrict__ scale_p,
                                    int out_size, int npts, int c, int C) {
    int s, G, G2, G3, B, N;
    get_dims(scale_p, out_size, npts, s, G, G2, G3, B, N);

    const int b0 = (int)((long long)c * B / C);
    const int b1 = (int)((long long)(c + 1) * B / C);
    // G is even -> G3 divisible by 4; float4 indices are exact.
    const size_t lo4 = (size_t)b0 * G3 / 4;
    const size_t hi4 = (size_t)b1 * G3 / 4;

    float4* o4 = reinterpret_cast<float4*>(out);
    const float4 z = make_float4(0.f, 0.f, 0.f, 0.f);
    const size_t stride = (size_t)gridDim.x * blockDim.x;
    for (size_t i = lo4 + (size_t)blockIdx.x * blockDim.x + threadIdx.x;
         i < hi4; i += stride) {
        o4[i] = z;
    }
}

// Scatter the points of batches [c*B/C, (c+1)*B/C).
__global__ void gridding_scatter_chunk(const float* __restrict__ pts,
                                       const int* __restrict__ scale_p,
                                       float* __restrict__ out,
                                       int npts, int out_size, int c, int C) {
    int s, G, G2, G3, B, N;
    get_dims(scale_p, out_size, npts, s, G, G2, G3, B, N);

    const int b0 = (int)((long long)c * B / C);
    const int b1 = (int)((long long)(c + 1) * B / C);
    const int i_lo = b0 * N;
    const int i_hi = b1 * N;

    const float fs = (float)s;
    const int stride = gridDim.x * blockDim.x;

    for (int i = i_lo + blockIdx.x * blockDim.x + threadIdx.x;
         i < i_hi; i += stride) {
        const int b = i / N;

        const float px = pts[3 * i + 0] * fs;
        const float py = pts[3 * i + 1] * fs;
        const float pz = pts[3 * i + 2] * fs;

        // Reference drops points whose scaled coords sum to exactly 0.
        const float m = (((px + py) + pz) != 0.0f) ? 1.0f : 0.0f;

        const float lx = floorf(px);
        const float ly = floorf(py);
        const float lz = floorf(pz);
        const float fx = px - lx;
        const float fy = py - ly;
        const float fz = pz - lz;

        const int bx = (int)lx + s;
        const int by = (int)ly + s;
        const int bz = (int)lz + s;

        const float wx0 = (1.0f - fx) * m;
        const float wx1 = fx * m;
        const float wy0 = 1.0f - fy;
        const float wy1 = fy;
        const float wz0 = 1.0f - fz;
        const float wz1 = fz;

        const float w00 = wx0 * wy0;
        const float w01 = wx0 * wy1;
        const float w10 = wx1 * wy0;
        const float w11 = wx1 * wy1;

        float* o = out + (size_t)b * G3 + ((size_t)bx * G + by) * G + bz;

        atomicAdd(o,              w00 * wz0);
        atomicAdd(o + 1,          w00 * wz1);
        atomicAdd(o + G,          w01 * wz0);
        atomicAdd(o + G + 1,      w01 * wz1);
        atomicAdd(o + G2,         w10 * wz0);
        atomicAdd(o + G2 + 1,     w10 * wz1);
        atomicAdd(o + G2 + G,     w11 * wz0);
        atomicAdd(o + G2 + G + 1, w11 * wz1);
    }
}

static const int kChunks = 8;

extern "C" void kernel_launch(void* const* d_in, const int* in_sizes, int n_in,
                              void* d_out, int out_size) {
    const float* pts = (const float*)d_in[0];
    const int* scale_p = (const int*)d_in[1];
    float* out = (float*)d_out;

    const int npts = in_sizes[0] / 3;

    // One-time creation of the helper stream + events (host-side resources,
    // no device memory allocation).
    static cudaStream_t sZ = nullptr;
    static cudaEvent_t evFork = nullptr;
    static cudaEvent_t evZ[kChunks];
    static cudaEvent_t evS[kChunks];
    if (sZ == nullptr) {
        cudaStreamCreateWithFlags(&sZ, cudaStreamNonBlocking);
        cudaEventCreateWithFlags(&evFork, cudaEventDisableTiming);
        for (int c = 0; c < kChunks; c++) {
            cudaEventCreateWithFlags(&evZ[c], cudaEventDisableTiming);
            cudaEventCreateWithFlags(&evS[c], cudaEventDisableTiming);
        }
    }

    const int threads = 256;
    // Per-chunk launch sizes (grid-stride loops absorb any rounding).
    int blocksZ = (out_size / kChunks / 4 + threads - 1) / threads;
    if (blocksZ > 2048) blocksZ = 2048;
    if (blocksZ < 1) blocksZ = 1;
    int blocksS = (npts / kChunks + threads - 1) / threads + 2;

    // Fork the zeroing stream off the capture stream.
    cudaEventRecord(evFork, 0);
    cudaStreamWaitEvent(sZ, evFork, 0);

    for (int c = 0; c < kChunks; c++) {
        // Rate-limit: don't zero more than one chunk ahead of the scatters,
        // so at most ~2 chunks of output are hot in L2 at a time.
        if (c >= 2) cudaStreamWaitEvent(sZ, evS[c - 2], 0);

        gridding_zero_chunk<<<blocksZ, threads, 0, sZ>>>(
            out, scale_p, out_size, npts, c, kChunks);
        cudaEventRecord(evZ[c], sZ);

        // Scatter chunk c on the capture stream once its zeros are in L2.
        cudaStreamWaitEvent(0, evZ[c], 0);
        gridding_scatter_chunk<<<blocksS, threads>>>(
            pts, scale_p, out, npts, out_size, c, kChunks);
        cudaEventRecord(evS[c], 0);
    }
    // Join: the last scatter already waits on evZ[kChunks-1], the final op on
    // sZ, so the side stream is fully joined into the capture stream.
}